// round 1
// baseline (speedup 1.0000x reference)
#include <cuda_runtime.h>

// Problem constants (shapes are fixed by setup_inputs):
//   x: (512, 256, 16, 16) fp32 -> (b=4, v=128, c=256, hw=256)
//   C = 256, K_conv = 768 (3 temporal taps x 256 channels)
//
// Key analytic simplification: sim <= 0 everywhere, so
// where(sim < 0.05, 100.0, sim) makes sim constant; top_k ties break to the
// lowest indices -> idx = [0,1,2,3] for every (b,t). Graph edges are fixed:
//   t*256 <-> (t+1)*256 + j, j in {0..3}, t in 0..126, plus self loops.
// GCN aggregation is identity (+bg) for all nodes except p<4 columns.

#define NB 4
#define NV 128
#define NC 256
#define NP 256
#define NELT (NB*NC*NV*NP)   // 33554432

__device__ __align__(16) float g_buf1[NELT];       // xd (b,c,t,p), later gcn-out (b,t,c,p)
__device__ __align__(16) float g_buf2[NELT];       // xl (b,c,t,p)
__device__ __align__(16) float g_w0[768 * 256];    // reordered Wd: [(k*256+i)][o]
__device__ __align__(16) float g_w1[768 * 256];    // reordered Wu

// ---------------------------------------------------------------------------
// Reorder conv weights (o,i,k) -> [(k*256+i)*256 + o]  (K-major for GEMM)
// ---------------------------------------------------------------------------
__global__ void reorder_w(const float* __restrict__ Wd, const float* __restrict__ Wu) {
    int n = blockIdx.x * 256 + threadIdx.x;        // n = k*65536 + i*256 + o
    int o = n & 255;
    int i = (n >> 8) & 255;
    int k = n >> 16;
    int src = (o * 256 + i) * 3 + k;
    g_w0[n] = Wd[src];
    g_w1[n] = Wu[src];
}

// ---------------------------------------------------------------------------
// Tiled SGEMM: C[256x256] per (b,t), C[o,p] = sum_k A[k,o]*B[k,p]
// MODE 0: temporal conv Wd on x           (K=768, masked rows at boundaries)
// MODE 1: xl = Wg^T @ xd                   (K=256)
// MODE 2: temporal conv Wu on gcn output  (K=768, masked), epilogue s2/t2
// Block = 256 threads, 128x128 tile, 8x8 per thread (4+4 split), KT=8,
// double-buffered shared memory.
// ---------------------------------------------------------------------------
template <int MODE>
__global__ void __launch_bounds__(256, 2) gemm256(
    const float* __restrict__ Ap,
    const float* __restrict__ Bp,
    float* __restrict__ Cp,
    const float* __restrict__ scale,
    const float* __restrict__ shift)
{
    constexpr int K = (MODE == 1) ? 256 : 768;
    const int z = blockIdx.z;
    const int b = z >> 7;
    const int t = z & 127;

    const float* A = (MODE == 0) ? g_w0 : (MODE == 2) ? g_w1 : Ap;
    const float* Broot = (MODE == 0) ? Bp : g_buf1;
    float* Croot = (MODE == 0) ? g_buf1 : (MODE == 1) ? g_buf2 : Cp;

    long bOff;
    int rs, kLo, kHi;
    if (MODE != 1) {
        // B rows k' = k*256+i live at frame (t+k-1): 3 contiguous frames.
        bOff = ((long)(b * 128 + t) - 1) * 65536;
        rs = 256;
        kLo = (t == 0) ? 256 : 0;
        kHi = (t == 127) ? 512 : 768;
    } else {
        // xd layout (b,c,t,p): row c stride 32768
        bOff = ((long)b << 23) + t * 256;
        rs = 32768;
        kLo = 0;
        kHi = 256;
    }
    long cOff;
    int cs;
    if (MODE == 2) { cOff = (long)(b * 128 + t) * 65536; cs = 256; }
    else           { cOff = ((long)b << 23) + t * 256;   cs = 32768; }

    const int tid = threadIdx.x;
    const int tx = tid & 15;
    const int ty = tid >> 4;
    const int oc0 = blockIdx.y * 128;
    const int pc0 = blockIdx.x * 128;

    __shared__ float As[2][8][128];
    __shared__ float Bs[2][8][128];

    const int lrow = tid >> 5;          // 0..7
    const int lcol = (tid & 31) * 4;    // 0..124

    float acc[8][8];
#pragma unroll
    for (int i = 0; i < 8; ++i)
#pragma unroll
        for (int j = 0; j < 8; ++j) acc[i][j] = 0.f;

    // prologue: load slab 0
    {
        int kr = lrow;
        float4 av = *(const float4*)(A + (size_t)kr * 256 + oc0 + lcol);
        float4 bv = make_float4(0.f, 0.f, 0.f, 0.f);
        if (kr >= kLo && kr < kHi)
            bv = *(const float4*)(Broot + bOff + (long)kr * rs + pc0 + lcol);
        *(float4*)&As[0][lrow][lcol] = av;
        *(float4*)&Bs[0][lrow][lcol] = bv;
    }
    __syncthreads();

    int cur = 0;
    for (int k0 = 0; k0 < K; k0 += 8) {
        const int kn = k0 + 8;
        float4 pav, pbv;
        if (kn < K) {
            int kr = kn + lrow;
            pav = *(const float4*)(A + (size_t)kr * 256 + oc0 + lcol);
            pbv = make_float4(0.f, 0.f, 0.f, 0.f);
            if (kr >= kLo && kr < kHi)
                pbv = *(const float4*)(Broot + bOff + (long)kr * rs + pc0 + lcol);
        }
#pragma unroll
        for (int kk = 0; kk < 8; ++kk) {
            float4 a0 = *(const float4*)&As[cur][kk][ty * 4];
            float4 a1 = *(const float4*)&As[cur][kk][64 + ty * 4];
            float4 b0 = *(const float4*)&Bs[cur][kk][tx * 4];
            float4 b1 = *(const float4*)&Bs[cur][kk][64 + tx * 4];
            float ar[8] = {a0.x, a0.y, a0.z, a0.w, a1.x, a1.y, a1.z, a1.w};
            float br[8] = {b0.x, b0.y, b0.z, b0.w, b1.x, b1.y, b1.z, b1.w};
#pragma unroll
            for (int i = 0; i < 8; ++i)
#pragma unroll
                for (int j = 0; j < 8; ++j)
                    acc[i][j] += ar[i] * br[j];
        }
        if (kn < K) {
            *(float4*)&As[cur ^ 1][lrow][lcol] = pav;
            *(float4*)&Bs[cur ^ 1][lrow][lcol] = pbv;
            __syncthreads();
            cur ^= 1;
        }
    }

    // epilogue: optional per-o scale/shift, float4 stores
#pragma unroll
    for (int i = 0; i < 8; ++i) {
        int r = (i < 4) ? (ty * 4 + i) : (64 + ty * 4 + (i - 4));
        int o = oc0 + r;
        float sv = 1.f, tv = 0.f;
        if (MODE != 1) { sv = scale[o]; tv = shift[o]; }
        float4 v0, v1;
        v0.x = acc[i][0] * sv + tv; v0.y = acc[i][1] * sv + tv;
        v0.z = acc[i][2] * sv + tv; v0.w = acc[i][3] * sv + tv;
        v1.x = acc[i][4] * sv + tv; v1.y = acc[i][5] * sv + tv;
        v1.z = acc[i][6] * sv + tv; v1.w = acc[i][7] * sv + tv;
        float* crow = Croot + cOff + (long)o * cs + pc0;
        *(float4*)(crow + tx * 4) = v0;
        *(float4*)(crow + 64 + tx * 4) = v1;
    }
}

// ---------------------------------------------------------------------------
// GCN aggregation (edges are the fixed idx=[0,1,2,3] graph) + bias, and
// transpose (b,c,t,p) -> (b,t,c,p) so the final conv reads like kernel 1.
//   out[n] = dinv[n]^2 * xl[n] + dinv[n] * sum_in dinv[s]*xl[s] + bg
// Only p<4 nodes are non-trivial.
// ---------------------------------------------------------------------------
__global__ void gcn_correct(const float* __restrict__ bg) {
    unsigned n = blockIdx.x * 256u + threadIdx.x;
    int p = n & 255;
    int t = (n >> 8) & 127;
    int c = (n >> 15) & 255;
    int b = n >> 23;

    const float* base = g_buf2 + ((size_t)b << 23) + ((size_t)c << 15);
    float v = base[t * 256 + p];
    float outv;

    const float r5 = 0.4472135954999579f;   // 1/sqrt(5)
    const float r6 = 0.4082482904638631f;   // 1/sqrt(6)
    const float r2 = 0.7071067811865476f;   // 1/sqrt(2)

    if (p >= 4 || (p > 0 && t == 0)) {
        outv = v;                            // deg 1, self loop only
    } else if (p == 0) {
        float d0 = (t == 0) ? r5 : ((t == 127) ? r2 : r6);
        float s = 0.f;
        if (t <= 126) {
            float d10 = (t + 1 == 127) ? r2 : r6;     // dinv(t+1, 0)
            s += d10 * base[(t + 1) * 256];
            s += r2 * (base[(t + 1) * 256 + 1] +
                       base[(t + 1) * 256 + 2] +
                       base[(t + 1) * 256 + 3]);      // dinv(t+1, j>=1) = r2
        }
        if (t >= 1) {
            float dm = (t == 1) ? r5 : r6;            // dinv(t-1, 0)
            s += dm * base[(t - 1) * 256];
        }
        outv = d0 * d0 * v + d0 * s;
    } else {  // p in 1..3, t >= 1: deg 2, one in-edge from (t-1, 0)
        float dm = (t == 1) ? r5 : r6;
        outv = 0.5f * v + r2 * dm * base[(t - 1) * 256];
    }
    outv += bg[c];
    // write layout (b, t, c, p)
    g_buf1[(((size_t)(b * 128 + t) * 256 + c) << 8) + p] = outv;
}

// ---------------------------------------------------------------------------
extern "C" void kernel_launch(void* const* d_in, const int* in_sizes, int n_in,
                              void* d_out, int out_size) {
    (void)in_sizes; (void)n_in; (void)out_size;
    const float* x  = (const float*)d_in[0];
    // d_in[1] = batch (int scalar, value 4) - shapes hardcoded
    const float* Wd = (const float*)d_in[2];
    const float* s1 = (const float*)d_in[3];
    const float* t1 = (const float*)d_in[4];
    const float* Wg = (const float*)d_in[5];
    const float* bg = (const float*)d_in[6];
    const float* Wu = (const float*)d_in[7];
    const float* s2 = (const float*)d_in[8];
    const float* t2 = (const float*)d_in[9];
    float* out = (float*)d_out;

    reorder_w<<<768, 256>>>(Wd, Wu);

    dim3 blk(256);
    dim3 grd(2, 2, 512);
    // xd = tconv(x, Wd)*s1 + t1           -> g_buf1 (b,c,t,p)
    gemm256<0><<<grd, blk>>>(nullptr, x, nullptr, s1, t1);
    // xl = Wg^T @ xd                      -> g_buf2 (b,c,t,p)
    gemm256<1><<<grd, blk>>>(Wg, nullptr, nullptr, nullptr, nullptr);
    // gcn aggregation + bg + transpose    -> g_buf1 (b,t,c,p)
    gcn_correct<<<NELT / 256, 256>>>(bg);
    // xu = tconv(gcnout, Wu)*s2 + t2      -> d_out (tlen,c,h,w)
    gemm256<2><<<grd, blk>>>(nullptr, nullptr, out, s2, t2);
}

// round 4
// speedup vs baseline: 1.0003x; 1.0003x over previous
#include <cuda_runtime.h>

// Problem constants (shapes are fixed by setup_inputs):
//   x: (512, 256, 16, 16) fp32 -> (b=4, v=128, c=256, hw=256)
//   C = 256, K_conv = 768 (3 temporal taps x 256 channels)
//
// Key analytic simplification: sim <= 0 everywhere, so
// where(sim < 0.05, 100.0, sim) makes sim constant; top_k ties break to the
// lowest indices -> idx = [0,1,2,3] for every (b,t). Graph edges are fixed:
//   t*256 <-> (t+1)*256 + j, j in {0..3}, t in 0..126, plus self loops.
// GCN aggregation is identity (+bg) for all nodes except p<4 columns.

#define NB 4
#define NV 128
#define NC 256
#define NP 256
#define NELT (NB*NC*NV*NP)   // 33554432

__device__ __align__(16) float g_buf1[NELT];       // xd (b,c,t,p), later gcn-out (b,t,c,p)
__device__ __align__(16) float g_buf2[NELT];       // xl (b,c,t,p)
__device__ __align__(16) float g_w0[768 * 256];    // reordered Wd: [(k*256+i)][o]
__device__ __align__(16) float g_w1[768 * 256];    // reordered Wu

// ---------------------------------------------------------------------------
// Reorder conv weights (o,i,k) -> [(k*256+i)*256 + o]  (K-major for GEMM)
// ---------------------------------------------------------------------------
__global__ void reorder_w(const float* __restrict__ Wd, const float* __restrict__ Wu) {
    int n = blockIdx.x * 256 + threadIdx.x;        // n = k*65536 + i*256 + o
    int o = n & 255;
    int i = (n >> 8) & 255;
    int k = n >> 16;
    int src = (o * 256 + i) * 3 + k;
    g_w0[n] = Wd[src];
    g_w1[n] = Wu[src];
}

// ---------------------------------------------------------------------------
// Tiled SGEMM: C[256x256] per (b,t), C[o,p] = sum_k A[k,o]*B[k,p]
// MODE 0: temporal conv Wd on x           (K=768, masked rows at boundaries)
// MODE 1: xl = Wg^T @ xd                   (K=256)
// MODE 2: temporal conv Wu on gcn output  (K=768, masked), epilogue s2/t2
// Block = 256 threads, 128x128 tile, 8x8 per thread (4+4 split), KT=8,
// double-buffered shared memory.
// ---------------------------------------------------------------------------
template <int MODE>
__global__ void __launch_bounds__(256, 2) gemm256(
    const float* __restrict__ Ap,
    const float* __restrict__ Bp,
    float* __restrict__ Cp,
    const float* __restrict__ scale,
    const float* __restrict__ shift)
{
    constexpr int K = (MODE == 1) ? 256 : 768;
    const int z = blockIdx.z;
    const int b = z >> 7;
    const int t = z & 127;

    const float* A = (MODE == 0) ? g_w0 : (MODE == 2) ? g_w1 : Ap;
    const float* Broot = (MODE == 0) ? Bp : g_buf1;
    float* Croot = (MODE == 0) ? g_buf1 : (MODE == 1) ? g_buf2 : Cp;

    long bOff;
    int rs, kLo, kHi;
    if (MODE != 1) {
        // B rows k' = k*256+i live at frame (t+k-1): 3 contiguous frames.
        bOff = ((long)(b * 128 + t) - 1) * 65536;
        rs = 256;
        kLo = (t == 0) ? 256 : 0;
        kHi = (t == 127) ? 512 : 768;
    } else {
        // xd layout (b,c,t,p): row c stride 32768
        bOff = ((long)b << 23) + t * 256;
        rs = 32768;
        kLo = 0;
        kHi = 256;
    }
    long cOff;
    int cs;
    if (MODE == 2) { cOff = (long)(b * 128 + t) * 65536; cs = 256; }
    else           { cOff = ((long)b << 23) + t * 256;   cs = 32768; }

    const int tid = threadIdx.x;
    const int tx = tid & 15;
    const int ty = tid >> 4;
    const int oc0 = blockIdx.y * 128;
    const int pc0 = blockIdx.x * 128;

    __shared__ float As[2][8][128];
    __shared__ float Bs[2][8][128];

    const int lrow = tid >> 5;          // 0..7
    const int lcol = (tid & 31) * 4;    // 0..124

    float acc[8][8];
#pragma unroll
    for (int i = 0; i < 8; ++i)
#pragma unroll
        for (int j = 0; j < 8; ++j) acc[i][j] = 0.f;

    // prologue: load slab 0
    {
        int kr = lrow;
        float4 av = *(const float4*)(A + (size_t)kr * 256 + oc0 + lcol);
        float4 bv = make_float4(0.f, 0.f, 0.f, 0.f);
        if (kr >= kLo && kr < kHi)
            bv = *(const float4*)(Broot + bOff + (long)kr * rs + pc0 + lcol);
        *(float4*)&As[0][lrow][lcol] = av;
        *(float4*)&Bs[0][lrow][lcol] = bv;
    }
    __syncthreads();

    int cur = 0;
    for (int k0 = 0; k0 < K; k0 += 8) {
        const int kn = k0 + 8;
        float4 pav, pbv;
        if (kn < K) {
            int kr = kn + lrow;
            pav = *(const float4*)(A + (size_t)kr * 256 + oc0 + lcol);
            pbv = make_float4(0.f, 0.f, 0.f, 0.f);
            if (kr >= kLo && kr < kHi)
                pbv = *(const float4*)(Broot + bOff + (long)kr * rs + pc0 + lcol);
        }
#pragma unroll
        for (int kk = 0; kk < 8; ++kk) {
            float4 a0 = *(const float4*)&As[cur][kk][ty * 4];
            float4 a1 = *(const float4*)&As[cur][kk][64 + ty * 4];
            float4 b0 = *(const float4*)&Bs[cur][kk][tx * 4];
            float4 b1 = *(const float4*)&Bs[cur][kk][64 + tx * 4];
            float ar[8] = {a0.x, a0.y, a0.z, a0.w, a1.x, a1.y, a1.z, a1.w};
            float br[8] = {b0.x, b0.y, b0.z, b0.w, b1.x, b1.y, b1.z, b1.w};
#pragma unroll
            for (int i = 0; i < 8; ++i)
#pragma unroll
                for (int j = 0; j < 8; ++j)
                    acc[i][j] += ar[i] * br[j];
        }
        if (kn < K) {
            *(float4*)&As[cur ^ 1][lrow][lcol] = pav;
            *(float4*)&Bs[cur ^ 1][lrow][lcol] = pbv;
            __syncthreads();
            cur ^= 1;
        }
    }

    // epilogue: optional per-o scale/shift, float4 stores
#pragma unroll
    for (int i = 0; i < 8; ++i) {
        int r = (i < 4) ? (ty * 4 + i) : (64 + ty * 4 + (i - 4));
        int o = oc0 + r;
        float sv = 1.f, tv = 0.f;
        if (MODE != 1) { sv = scale[o]; tv = shift[o]; }
        float4 v0, v1;
        v0.x = acc[i][0] * sv + tv; v0.y = acc[i][1] * sv + tv;
        v0.z = acc[i][2] * sv + tv; v0.w = acc[i][3] * sv + tv;
        v1.x = acc[i][4] * sv + tv; v1.y = acc[i][5] * sv + tv;
        v1.z = acc[i][6] * sv + tv; v1.w = acc[i][7] * sv + tv;
        float* crow = Croot + cOff + (long)o * cs + pc0;
        *(float4*)(crow + tx * 4) = v0;
        *(float4*)(crow + 64 + tx * 4) = v1;
    }
}

// ---------------------------------------------------------------------------
// GCN aggregation (edges are the fixed idx=[0,1,2,3] graph) + bias, and
// transpose (b,c,t,p) -> (b,t,c,p) so the final conv reads like kernel 1.
//   out[n] = dinv[n]^2 * xl[n] + dinv[n] * sum_in dinv[s]*xl[s] + bg
// Only p<4 nodes are non-trivial.
// ---------------------------------------------------------------------------
__global__ void gcn_correct(const float* __restrict__ bg) {
    unsigned n = blockIdx.x * 256u + threadIdx.x;
    int p = n & 255;
    int t = (n >> 8) & 127;
    int c = (n >> 15) & 255;
    int b = n >> 23;

    const float* base = g_buf2 + ((size_t)b << 23) + ((size_t)c << 15);
    float v = base[t * 256 + p];
    float outv;

    const float r5 = 0.4472135954999579f;   // 1/sqrt(5)
    const float r6 = 0.4082482904638631f;   // 1/sqrt(6)
    const float r2 = 0.7071067811865476f;   // 1/sqrt(2)

    if (p >= 4 || (p > 0 && t == 0)) {
        outv = v;                            // deg 1, self loop only
    } else if (p == 0) {
        float d0 = (t == 0) ? r5 : ((t == 127) ? r2 : r6);
        float s = 0.f;
        if (t <= 126) {
            float d10 = (t + 1 == 127) ? r2 : r6;     // dinv(t+1, 0)
            s += d10 * base[(t + 1) * 256];
            s += r2 * (base[(t + 1) * 256 + 1] +
                       base[(t + 1) * 256 + 2] +
                       base[(t + 1) * 256 + 3]);      // dinv(t+1, j>=1) = r2
        }
        if (t >= 1) {
            float dm = (t == 1) ? r5 : r6;            // dinv(t-1, 0)
            s += dm * base[(t - 1) * 256];
        }
        outv = d0 * d0 * v + d0 * s;
    } else {  // p in 1..3, t >= 1: deg 2, one in-edge from (t-1, 0)
        float dm = (t == 1) ? r5 : r6;
        outv = 0.5f * v + r2 * dm * base[(t - 1) * 256];
    }
    outv += bg[c];
    // write layout (b, t, c, p)
    g_buf1[(((size_t)(b * 128 + t) * 256 + c) << 8) + p] = outv;
}

// ---------------------------------------------------------------------------
extern "C" void kernel_launch(void* const* d_in, const int* in_sizes, int n_in,
                              void* d_out, int out_size) {
    (void)in_sizes; (void)n_in; (void)out_size;
    const float* x  = (const float*)d_in[0];
    // d_in[1] = batch (int scalar, value 4) - shapes hardcoded
    const float* Wd = (const float*)d_in[2];
    const float* s1 = (const float*)d_in[3];
    const float* t1 = (const float*)d_in[4];
    const float* Wg = (const float*)d_in[5];
    const float* bg = (const float*)d_in[6];
    const float* Wu = (const float*)d_in[7];
    const float* s2 = (const float*)d_in[8];
    const float* t2 = (const float*)d_in[9];
    float* out = (float*)d_out;

    reorder_w<<<768, 256>>>(Wd, Wu);

    dim3 blk(256);
    dim3 grd(2, 2, 512);
    // xd = tconv(x, Wd)*s1 + t1           -> g_buf1 (b,c,t,p)
    gemm256<0><<<grd, blk>>>(nullptr, x, nullptr, s1, t1);
    // xl = Wg^T @ xd                      -> g_buf2 (b,c,t,p)
    gemm256<1><<<grd, blk>>>(Wg, nullptr, nullptr, nullptr, nullptr);
    // gcn aggregation + bg + transpose    -> g_buf1 (b,t,c,p)
    gcn_correct<<<NELT / 256, 256>>>(bg);
    // xu = tconv(gcnout, Wu)*s2 + t2      -> d_out (tlen,c,h,w)
    gemm256<2><<<grd, blk>>>(nullptr, nullptr, out, s2, t2);
}

// round 12
// speedup vs baseline: 2.2838x; 2.2831x over previous
#include <cuda_runtime.h>

typedef unsigned int u32;

// Shapes fixed by setup_inputs: b=4, v=128, c=256, hw=256.
// Validated analytic simplification: top_k indices are the constant [0,1,2,3];
// graph fixed; GCN aggregation nontrivial only for p<4.
#define NELT (4*256*128*256)

__device__ __align__(16) float g_T0 [NELT];   // x transposed per frame [n][p][c] (tf32)
__device__ __align__(16) float g_xdT[NELT];   // xd [n][p][c] (tf32, post s1/t1)
__device__ __align__(16) float g_xlT[NELT];   // xl [n][p][c] (fp32)
__device__ __align__(16) float g_G  [NELT];   // gcn out [n][p][c] (tf32, post +bg)
// packed weights, tf32-rounded, chunk-major [cc][o 256][k 32]:
//   cc 0..23 : Wd (tap = cc/8, i = (cc%8)*32 + k)
//   cc 24..47: Wu (same)
//   cc 48..55: Wg^T (A[o][k] = Wg[k][o])
__device__ __align__(16) float g_wp[56 * 8192];

// ---------------------------------------------------------------------------
__device__ __forceinline__ u32 s2u(const void* p) {
    u32 a;
    asm("{ .reg .u64 t; cvta.to.shared.u64 t, %1; cvt.u32.u64 %0, t; }" : "=r"(a) : "l"(p));
    return a;
}
__device__ __forceinline__ float tf32r(float v) {
    u32 u; asm("cvt.rna.tf32.f32 %0, %1;" : "=r"(u) : "f"(v));
    return __uint_as_float(u);
}
__device__ __forceinline__ void mma8(float* c, const u32* a, const u32* b) {
    asm volatile(
        "mma.sync.aligned.m16n8k8.row.col.f32.tf32.tf32.f32 "
        "{%0,%1,%2,%3}, {%4,%5,%6,%7}, {%8,%9}, {%0,%1,%2,%3};"
        : "+f"(c[0]), "+f"(c[1]), "+f"(c[2]), "+f"(c[3])
        : "r"(a[0]), "r"(a[1]), "r"(a[2]), "r"(a[3]), "r"(b[0]), "r"(b[1]));
}
#define CPA(sdst, gsrc) \
    asm volatile("cp.async.cg.shared.global [%0], [%1], 16;" :: "r"(sdst), "l"(gsrc))
#define CPC() asm volatile("cp.async.commit_group;" ::: "memory")
#define CPW(N) asm volatile("cp.async.wait_group %0;" :: "n"(N) : "memory")

// ---------------------------------------------------------------------------
// Pre-pass 1: per-frame transpose x [n][c][p] -> g_T0 [n][p][c], tf32 round.
// ---------------------------------------------------------------------------
__global__ void transpose_x(const float* __restrict__ x) {
    __shared__ float tile[32][33];
    int n = blockIdx.z;
    int c0 = blockIdx.y * 32, p0 = blockIdx.x * 32;
    int tx = threadIdx.x, ty = threadIdx.y;
    const float* src = x + (size_t)n * 65536;
    float* dst = g_T0 + (size_t)n * 65536;
#pragma unroll
    for (int i = 0; i < 32; i += 8)
        tile[ty + i][tx] = src[(c0 + ty + i) * 256 + p0 + tx];
    __syncthreads();
#pragma unroll
    for (int i = 0; i < 32; i += 8)
        dst[(p0 + ty + i) * 256 + c0 + tx] = tf32r(tile[tx][ty + i]);
}

// ---------------------------------------------------------------------------
// Pre-pass 2: pack weights chunk-major, tf32-rounded.
// ---------------------------------------------------------------------------
__global__ void reorder_w(const float* __restrict__ Wd, const float* __restrict__ Wg,
                          const float* __restrict__ Wu) {
    int idx = blockIdx.x * 256 + threadIdx.x;   // 56*8192
    int cc = idx >> 13;
    int o = (idx >> 5) & 255;
    int k = idx & 31;
    float v;
    if (cc < 48) {
        int w = cc / 24, lc = cc % 24;
        int tap = lc >> 3;
        int i = (lc & 7) * 32 + k;
        v = (w ? Wu : Wd)[(o * 256 + i) * 3 + tap];
    } else {
        int i = (cc - 48) * 32 + k;
        v = Wg[i * 256 + o];
    }
    g_wp[idx] = tf32r(v);
}

// ---------------------------------------------------------------------------
// tf32 mma.sync GEMM. Per CTA: D[o 128][p 128] for one frame.
//   MODE 0: xd = conv(x,Wd)*s1+t1    A=Wd,  B=g_T0 (3 frames) -> g_xdT [p][c]
//   MODE 1: xl = xd @ Wg             A=Wg^T,B=g_xdT           -> g_xlT [p][c]
//   MODE 2: out = conv(G,Wu)*s2+t2   A=Wu,  B=g_G (3 frames)  -> d_out [c][p]
// 256 threads / 8 warps (2x4), warp tile 64x32; K chunk 32, cp.async double
// buffer, smem row stride 36 words (fragment loads conflict-free).
// Epilogue staging stride = 132 words (16B-aligned row starts for float4).
// ---------------------------------------------------------------------------
template <int MODE>
__global__ void __launch_bounds__(256, 1) gemm_mma(float* __restrict__ Cout,
                                                   const float* __restrict__ scale,
                                                   const float* __restrict__ shift) {
    extern __shared__ float sm[];
    const u32 smem = s2u(sm);

    const int tid = threadIdx.x;
    const int wid = tid >> 5, lane = tid & 31;
    const int gid = lane >> 2, t4 = lane & 3;
    const int wm = wid >> 2, wn = wid & 3;
    const int p0 = blockIdx.x * 128, o0 = blockIdx.y * 128;
    const int n = blockIdx.z, t = n & 127;

    const float* Awb = g_wp + (MODE == 0 ? 0 : (MODE == 2 ? 24 * 8192 : 48 * 8192));
    const float* Act = (MODE == 0) ? g_T0 : (MODE == 1) ? g_xdT : g_G;
    const int f0 = (MODE == 1) ? t : (t > 0 ? t - 1 : 0);
    const int f1 = (MODE == 1) ? t : (t < 127 ? t + 1 : 127);
    const int NQ = (f1 - f0 + 1) * 8;

    // chunk loader: chunk q -> buffer bb (A tile then B tile, 4 float4 each)
    auto load_chunk = [&](int q, int bb) {
        const int f = f0 + (q >> 3), kc = q & 7;
        const int cc = (MODE == 1) ? kc : (f - t + 1) * 8 + kc;
        const float* Ab = Awb + (size_t)cc * 8192 + (size_t)o0 * 32;
        const float* Bb = Act + (size_t)(n + f - t) * 65536 + (size_t)p0 * 256 + kc * 32;
        const u32 sA = smem + (u32)(bb * 9216) * 4;
        const u32 sB = sA + 4608 * 4;
#pragma unroll
        for (int j = 0; j < 4; ++j) {
            int e = tid + j * 256;
            int row = e >> 3, kq = e & 7;
            u32 soff = (u32)(row * 36 + kq * 4) * 4;
            CPA(sA + soff, Ab + row * 32 + kq * 4);
            CPA(sB + soff, Bb + row * 256 + kq * 4);
        }
        CPC();
    };

    float acc[4][4][4];
#pragma unroll
    for (int i = 0; i < 4; ++i)
#pragma unroll
        for (int j = 0; j < 4; ++j)
#pragma unroll
            for (int e = 0; e < 4; ++e) acc[i][j][e] = 0.f;

    load_chunk(0, 0);
    for (int q = 0; q < NQ; ++q) {
        if (q + 1 < NQ) { load_chunk(q + 1, (q + 1) & 1); CPW(1); }
        else            { CPW(0); }
        __syncthreads();

        const u32* A = (const u32*)sm + (q & 1) * 9216;
        const u32* B = A + 4608;
#pragma unroll
        for (int ks = 0; ks < 4; ++ks) {
            u32 af[4][4], bf[4][2];
#pragma unroll
            for (int mi = 0; mi < 4; ++mi) {
                int m = wm * 64 + mi * 16 + gid;
                int base = m * 36 + ks * 8 + t4;
                af[mi][0] = A[base];
                af[mi][1] = A[base + 8 * 36];
                af[mi][2] = A[base + 4];
                af[mi][3] = A[base + 8 * 36 + 4];
            }
#pragma unroll
            for (int ni = 0; ni < 4; ++ni) {
                int p = wn * 32 + ni * 8 + gid;
                int base = p * 36 + ks * 8 + t4;
                bf[ni][0] = B[base];
                bf[ni][1] = B[base + 4];
            }
#pragma unroll
            for (int mi = 0; mi < 4; ++mi)
#pragma unroll
                for (int ni = 0; ni < 4; ++ni)
                    mma8(acc[mi][ni], af[mi], bf[ni]);
        }
        __syncthreads();
    }

    // ---------------- epilogue: stage through smem, coalesced rows ----------
    // Stage stride 132 words: row starts 16B-aligned (132*4 = 33*16).
    // MODE 0/1: stage [p][c] (write [n][p][c]); MODE 2: stage [c][p].
#pragma unroll
    for (int mi = 0; mi < 4; ++mi)
#pragma unroll
        for (int ni = 0; ni < 4; ++ni)
#pragma unroll
            for (int e = 0; e < 4; ++e) {
                int ol = wm * 64 + mi * 16 + gid + ((e >= 2) ? 8 : 0);
                int pl = wn * 32 + ni * 8 + 2 * t4 + (e & 1);
                if (MODE == 2) sm[ol * 132 + pl] = acc[mi][ni][e];
                else           sm[pl * 132 + ol] = acc[mi][ni][e];
            }
    __syncthreads();

#pragma unroll
    for (int it = 0; it < 16; ++it) {
        int idx = it * 256 + tid;
        int r = idx >> 5, qd = idx & 31;
        float4 v = *(const float4*)&sm[r * 132 + qd * 4];
        float* dst;
        if (MODE == 2) {
            int c = o0 + r;
            float sv = scale[c], tv = shift[c];
            v.x = v.x * sv + tv; v.y = v.y * sv + tv;
            v.z = v.z * sv + tv; v.w = v.w * sv + tv;
            dst = Cout + (size_t)n * 65536 + (size_t)c * 256 + p0;
        } else {
            if (MODE == 0) {
                const float4 sc = *(const float4*)(scale + o0 + qd * 4);
                const float4 sh = *(const float4*)(shift + o0 + qd * 4);
                v.x = tf32r(v.x * sc.x + sh.x); v.y = tf32r(v.y * sc.y + sh.y);
                v.z = tf32r(v.z * sc.z + sh.z); v.w = tf32r(v.w * sc.w + sh.w);
            }
            float* Cb = (MODE == 0) ? g_xdT : g_xlT;
            dst = Cb + (size_t)n * 65536 + (size_t)(p0 + r) * 256 + o0;
        }
        *(float4*)(dst + qd * 4) = v;
    }
}

// ---------------------------------------------------------------------------
// GCN aggregation on g_xlT [n][p][c] (+bg), tf32 -> g_G.
// ---------------------------------------------------------------------------
__global__ void gcn_k(const float* __restrict__ bg) {
    int nn = blockIdx.x * 256 + threadIdx.x;
    int c = nn & 255;
    int p = (nn >> 8) & 255;
    int tt = (nn >> 16) & 127;
    int b = nn >> 23;
    const float* B = g_xlT + ((size_t)b << 23);
    const float r5 = 0.4472135954999579f;
    const float r6 = 0.4082482904638631f;
    const float r2 = 0.7071067811865476f;

    float v = B[(((size_t)tt << 8) + p) * 256 + c];
    float outv;
    if (p >= 4 || (p > 0 && tt == 0)) {
        outv = v;
    } else if (p == 0) {
        float d0 = (tt == 0) ? r5 : ((tt == 127) ? r2 : r6);
        float s = 0.f;
        if (tt <= 126) {
            const float* nxt = B + (((size_t)(tt + 1) << 8)) * 256 + c;
            float d10 = (tt + 1 == 127) ? r2 : r6;
            s += d10 * nxt[0];
            s += r2 * (nxt[256] + nxt[512] + nxt[768]);
        }
        if (tt >= 1) {
            float dm = (tt == 1) ? r5 : r6;
            s += dm * B[(((size_t)(tt - 1) << 8)) * 256 + c];
        }
        outv = d0 * d0 * v + d0 * s;
    } else {
        float dm = (tt == 1) ? r5 : r6;
        outv = 0.5f * v + r2 * dm * B[(((size_t)(tt - 1) << 8)) * 256 + c];
    }
    g_G[nn] = tf32r(outv + bg[c]);
}

// ---------------------------------------------------------------------------
extern "C" void kernel_launch(void* const* d_in, const int* in_sizes, int n_in,
                              void* d_out, int out_size) {
    (void)in_sizes; (void)n_in; (void)out_size;
    const float* x  = (const float*)d_in[0];
    const float* Wd = (const float*)d_in[2];
    const float* s1 = (const float*)d_in[3];
    const float* t1 = (const float*)d_in[4];
    const float* Wg = (const float*)d_in[5];
    const float* bg = (const float*)d_in[6];
    const float* Wu = (const float*)d_in[7];
    const float* s2 = (const float*)d_in[8];
    const float* t2 = (const float*)d_in[9];
    float* out = (float*)d_out;

    const int SMEM = 73728;   // mainloop: 2*(4608+4608) words; epi: 128*132 words
    cudaFuncSetAttribute(gemm_mma<0>, cudaFuncAttributeMaxDynamicSharedMemorySize, SMEM);
    cudaFuncSetAttribute(gemm_mma<1>, cudaFuncAttributeMaxDynamicSharedMemorySize, SMEM);
    cudaFuncSetAttribute(gemm_mma<2>, cudaFuncAttributeMaxDynamicSharedMemorySize, SMEM);

    transpose_x<<<dim3(8, 8, 512), dim3(32, 8)>>>(x);
    reorder_w<<<1792, 256>>>(Wd, Wg, Wu);

    dim3 grd2(2, 2, 512);
    gemm_mma<0><<<grd2, 256, SMEM>>>(nullptr, s1, t1);           // -> g_xdT
    gemm_mma<1><<<grd2, 256, SMEM>>>(nullptr, nullptr, nullptr); // -> g_xlT
    gcn_k<<<NELT / 256, 256>>>(bg);                              // -> g_G
    gemm_mma<2><<<grd2, 256, SMEM>>>(out, s2, t2);               // -> d_out
}